// round 7
// baseline (speedup 1.0000x reference)
#include <cuda_runtime.h>
#include <cuda_bf16.h>
#include <cstdint>

// density[b,h,w] = sum_n gy[b,n,h] * gx[b,n,w]
//   gx/gy: per-label 1-D gaussians, each normalized by its own full-row sum.
// B=4, N=64, H=W=512. SINGLE fused kernel, grid (4,8,4) = 128 CTAs (1 wave):
//   Phase 0: adaptive-window row sums (half-window 7*sigma, clamped;
//            relative tail < e^-24 -> far under the 1e-3 tolerance)
//   Mainloop: 4 passes of K=16, DOUBLE-BUFFERED: gen(p+1) issued before
//            fma(p) so MUFU/STS fills FFMA2's spare issue slots.
//   FMA: register-tiled 4(h) x 8(w) per thread, packed f32x2 FMA.

#define B_  4
#define N_  64
#define HW_ 512
#define TW_ 128
#define TH_ 64
#define KP_ 16            // n per pass
#define NP_ 4             // passes

#define FMA2(d, a, bb, c) \
    asm("fma.rn.f32x2 %0, %1, %2, %3;" : "=l"(d) : "l"(a), "l"(bb), "l"(c))
#define PACK2(out, f) \
    asm("mov.b64 %0, {%1, %1};" : "=l"(out) : "r"(__float_as_uint(f)))

__global__ __launch_bounds__(256) void density_kernel(
    float* __restrict__ out,
    const float* __restrict__ labels,   // (B, N, 2)
    const float* __restrict__ sigma)    // (1,)
{
    __shared__ float sGx[2][KP_ * TW_];   // 2 x 8 KB  [n][w_local], pre-scaled
    __shared__ float sGy[2][KP_ * TH_];   // 2 x 4 KB  [n][h_local], raw exp
    __shared__ float sLx[N_], sLy[N_];    // label coords
    __shared__ float sSum[2 * N_];        // raw row sums: [0,64)=x, [64,128)=y
    __shared__ float sInv[N_];            // 1 / (sum_x[n] * sum_y[n])

    const int b     = blockIdx.z;
    const int wbase = blockIdx.x * TW_;
    const int hbase = blockIdx.y * TH_;
    const int t     = threadIdx.x;

    const float sg  = sigma[0];
    const float inv = 0.5f / (sg * sg);   // 1/(2 sigma^2)

    if (t < N_) {
        const float2 l = ((const float2*)labels)[b * N_ + t];
        sLx[t] = l.x;
        sLy[t] = l.y;
    }
    __syncthreads();

    // ---- Phase 0: adaptive-window row sums. 2 threads/row, nh px each,
    //      two independent FADD chains per thread. ----
    {
        const int r    = t >> 1;          // 0..127 (row: axis*64 + n)
        const int half = t & 1;
        const float c  = (r < N_) ? sLx[r] : sLy[r - N_];
        // half-window: 7 sigma (rel tail < e^-24), clamped to [16,256]
        const int nh   = min(256, max(16, (int)(7.0f * sg)));
        const int ci   = __float2int_rn(c);
        const int s0   = min(max(ci - nh, 0), HW_ - 2 * nh);
        const int beg  = s0 + half * nh;

        float s0a = 0.0f, s1a = 0.0f;
        int i = 0;
        for (; i + 1 < nh; i += 2) {
            const float d0 = (float)(beg + i)     - c;
            const float d1 = (float)(beg + i + 1) - c;
            s0a += __expf(-(d0 * d0) * inv);
            s1a += __expf(-(d1 * d1) * inv);
        }
        if (i < nh) {
            const float d0 = (float)(beg + i) - c;
            s0a += __expf(-(d0 * d0) * inv);
        }
        float s = s0a + s1a;
        s += __shfl_xor_sync(0xFFFFFFFFu, s, 1);
        if (half == 0) sSum[r] = s;
    }
    __syncthreads();
    if (t < N_)
        sInv[t] = __fdividef(1.0f, sSum[t] * sSum[N_ + t]);
    __syncthreads();

    // ---- accumulators: 4(h) x 8(w) per thread as f32x2 pairs ----
    const int tx = t & 15;    // w (x8 floats)
    const int ty = t >> 4;    // h (x4 floats)

    unsigned long long acc[4][4];
    #pragma unroll
    for (int i = 0; i < 4; i++)
        #pragma unroll
        for (int j = 0; j < 4; j++) acc[i][j] = 0ull;

    // tile generator: pass p -> labels [p*KP_, (p+1)*KP_), buffer buf
    auto gen = [&](int p, int buf) {
        const int n0 = p * KP_;
        #pragma unroll
        for (int i = t; i < KP_ * TW_; i += 256) {       // gx, scaled: 8/thread
            const int n = i >> 7;
            const float d = (float)(wbase + (i & 127)) - sLx[n0 + n];
            sGx[buf][i] = __expf(-(d * d) * inv) * sInv[n0 + n];
        }
        #pragma unroll
        for (int i = t; i < KP_ * TH_; i += 256) {       // gy, raw: 4/thread
            const int n = i >> 6;
            const float d = (float)(hbase + (i & 63)) - sLy[n0 + n];
            sGy[buf][i] = __expf(-(d * d) * inv);
        }
    };

    gen(0, 0);
    __syncthreads();

    // ---- pipelined mainloop: gen(p+1) overlaps fma(p) ----
    #pragma unroll
    for (int p = 0; p < NP_; p++) {
        const int buf = p & 1;
        if (p + 1 < NP_) gen(p + 1, buf ^ 1);   // fills FFMA2's spare slots

        const ulonglong2* sxp = (const ulonglong2*)sGx[buf]; // 32 ull2 / n-row
        const float4*     syp = (const float4*)sGy[buf];     // 16 f4  / n-row

        #pragma unroll 8
        for (int n = 0; n < KP_; n++) {
            const ulonglong2 bx0 = sxp[n * 32 + tx * 2 + 0];
            const ulonglong2 bx1 = sxp[n * 32 + tx * 2 + 1];
            const float4     gy4 = syp[n * 16 + ty];

            unsigned long long a0, a1, a2, a3;
            PACK2(a0, gy4.x); PACK2(a1, gy4.y);
            PACK2(a2, gy4.z); PACK2(a3, gy4.w);

            FMA2(acc[0][0], a0, bx0.x, acc[0][0]);
            FMA2(acc[0][1], a0, bx0.y, acc[0][1]);
            FMA2(acc[0][2], a0, bx1.x, acc[0][2]);
            FMA2(acc[0][3], a0, bx1.y, acc[0][3]);
            FMA2(acc[1][0], a1, bx0.x, acc[1][0]);
            FMA2(acc[1][1], a1, bx0.y, acc[1][1]);
            FMA2(acc[1][2], a1, bx1.x, acc[1][2]);
            FMA2(acc[1][3], a1, bx1.y, acc[1][3]);
            FMA2(acc[2][0], a2, bx0.x, acc[2][0]);
            FMA2(acc[2][1], a2, bx0.y, acc[2][1]);
            FMA2(acc[2][2], a2, bx1.x, acc[2][2]);
            FMA2(acc[2][3], a2, bx1.y, acc[2][3]);
            FMA2(acc[3][0], a3, bx0.x, acc[3][0]);
            FMA2(acc[3][1], a3, bx0.y, acc[3][1]);
            FMA2(acc[3][2], a3, bx1.x, acc[3][2]);
            FMA2(acc[3][3], a3, bx1.y, acc[3][3]);
        }
        if (p + 1 < NP_) __syncthreads();  // gen(p+2) may overwrite buf
    }

    // ---- Store: each h-row = 8 consecutive floats = 2x STG.128 ----
    #pragma unroll
    for (int i = 0; i < 4; i++) {
        const int h = hbase + ty * 4 + i;
        const int w = wbase + tx * 8;
        float4* dst = (float4*)(out + ((size_t)b * HW_ + h) * HW_ + w);
        dst[0] = *(const float4*)&acc[i][0];
        dst[1] = *(const float4*)&acc[i][2];
    }
}

// ---------------------------------------------------------------------------
// Launch: single kernel, single graph node.
// ---------------------------------------------------------------------------
extern "C" void kernel_launch(void* const* d_in, const int* in_sizes, int n_in,
                              void* d_out, int out_size)
{
    // d_in[0] = batch_images (unused, shape only)
    const float* labels = (const float*)d_in[1];  // (4, 64, 2)
    const float* sigma  = (const float*)d_in[2];  // (1,)
    float* out = (float*)d_out;                   // (4, 1, 512, 512)

    dim3 grid(HW_ / TW_, HW_ / TH_, B_);   // (4, 8, 4) = 128 CTAs
    density_kernel<<<grid, 256>>>(out, labels, sigma);
}

// round 8
// speedup vs baseline: 1.1830x; 1.1830x over previous
#include <cuda_runtime.h>
#include <cuda_bf16.h>
#include <cstdint>

// density[b,h,w] = sum_n gy[b,n,h] * gx[b,n,w]
//   gx/gy: per-label 1-D gaussians, each normalized by its own full-row sum.
// B=4, N=64, H=W=512. SINGLE fused kernel.
// R7 lesson (ncu): 8 warps/SM left the kernel latency-bound (issue 25%,
// fma 15.9% == serialized floor). This round: 64x64 tiles, 256 CTAs,
// 4 CTAs/SM (32 warps/SM) -> TLP covers LDS/MUFU latency.
//   Phase 0: adaptive-window row sums (half-window 7*sigma, clamped)
//   Mainloop: 4 passes of K=16, double-buffered gen/fma overlap.
//   gy stored pre-duplicated (v,v) so no packing insts in the hot loop:
//   per n-step: 3x LDS.128 + 8x fma.rn.f32x2.

#define B_  4
#define N_  64
#define HW_ 512
#define TW_ 64
#define TH_ 64
#define KP_ 16            // n per pass
#define NP_ 4             // passes

#define FMA2(d, a, bb, c) \
    asm("fma.rn.f32x2 %0, %1, %2, %3;" : "=l"(d) : "l"(a), "l"(bb), "l"(c))

__global__ __launch_bounds__(256, 4) void density_kernel(
    float* __restrict__ out,
    const float* __restrict__ labels,   // (B, N, 2)
    const float* __restrict__ sigma)    // (1,)
{
    __shared__ float  sGx[2][KP_ * TW_];    // 2 x 4 KB, [n][w], pre-scaled
    __shared__ float2 sGy[2][KP_ * TH_];    // 2 x 8 KB, [n][h], (v,v) pairs
    __shared__ float  sLx[N_], sLy[N_];
    __shared__ float  sSum[2 * N_];         // [0,64)=x sums, [64,128)=y sums
    __shared__ float  sInv[N_];             // 1 / (sum_x * sum_y)

    const int b     = blockIdx.z;
    const int wbase = blockIdx.x * TW_;
    const int hbase = blockIdx.y * TH_;
    const int t     = threadIdx.x;

    const float sg  = sigma[0];
    const float inv = 0.5f / (sg * sg);   // 1/(2 sigma^2)

    if (t < N_) {
        const float2 l = ((const float2*)labels)[b * N_ + t];
        sLx[t] = l.x;
        sLy[t] = l.y;
    }
    __syncthreads();

    // ---- Phase 0: adaptive-window row sums. 2 threads/row, nh px each. ----
    {
        const int r    = t >> 1;          // 0..127 (row: axis*64 + n)
        const int half = t & 1;
        const float c  = (r < N_) ? sLx[r] : sLy[r - N_];
        const int nh   = min(256, max(16, (int)(7.0f * sg)));  // 7 sigma
        const int ci   = __float2int_rn(c);
        const int s0   = min(max(ci - nh, 0), HW_ - 2 * nh);
        const int beg  = s0 + half * nh;

        float s0a = 0.0f, s1a = 0.0f;
        int i = 0;
        for (; i + 1 < nh; i += 2) {
            const float d0 = (float)(beg + i)     - c;
            const float d1 = (float)(beg + i + 1) - c;
            s0a += __expf(-(d0 * d0) * inv);
            s1a += __expf(-(d1 * d1) * inv);
        }
        if (i < nh) {
            const float d0 = (float)(beg + i) - c;
            s0a += __expf(-(d0 * d0) * inv);
        }
        float s = s0a + s1a;
        s += __shfl_xor_sync(0xFFFFFFFFu, s, 1);
        if (half == 0) sSum[r] = s;
    }
    __syncthreads();
    if (t < N_)
        sInv[t] = __fdividef(1.0f, sSum[t] * sSum[N_ + t]);
    __syncthreads();

    // ---- accumulators: 4(h) x 4(w) per thread as f32x2 pairs ----
    const int tx = t & 15;    // w (x4 floats)
    const int ty = t >> 4;    // h (x4 floats)

    unsigned long long acc[4][2];
    #pragma unroll
    for (int i = 0; i < 4; i++) { acc[i][0] = 0ull; acc[i][1] = 0ull; }

    // tile generator: pass p -> labels [p*KP_, (p+1)*KP_), buffer buf
    auto gen = [&](int p, int buf) {
        const int n0 = p * KP_;
        #pragma unroll
        for (int i = t; i < KP_ * TW_; i += 256) {     // gx scaled: 4/thread
            const int n = i >> 6;
            const float d = (float)(wbase + (i & 63)) - sLx[n0 + n];
            sGx[buf][i] = __expf(-(d * d) * inv) * sInv[n0 + n];
        }
        #pragma unroll
        for (int i = t; i < KP_ * TH_; i += 256) {     // gy dup: 4/thread
            const int n = i >> 6;
            const float d = (float)(hbase + (i & 63)) - sLy[n0 + n];
            const float v = __expf(-(d * d) * inv);
            sGy[buf][i] = make_float2(v, v);
        }
    };

    gen(0, 0);
    __syncthreads();

    // ---- pipelined mainloop: gen(p+1) overlaps fma(p) ----
    #pragma unroll
    for (int p = 0; p < NP_; p++) {
        const int buf = p & 1;
        if (p + 1 < NP_) gen(p + 1, buf ^ 1);

        const ulonglong2* sxp = (const ulonglong2*)sGx[buf];  // 16 ull2 /n-row
        const ulonglong2* syp = (const ulonglong2*)sGy[buf];  // 32 ull2 /n-row

        #pragma unroll 4
        for (int n = 0; n < KP_; n++) {
            const ulonglong2 bx  = sxp[n * 16 + tx];          // 4 gx (2 pairs)
            const ulonglong2 ay0 = syp[n * 32 + ty * 2 + 0];  // gy h0,h1 dup
            const ulonglong2 ay1 = syp[n * 32 + ty * 2 + 1];  // gy h2,h3 dup

            FMA2(acc[0][0], ay0.x, bx.x, acc[0][0]);
            FMA2(acc[0][1], ay0.x, bx.y, acc[0][1]);
            FMA2(acc[1][0], ay0.y, bx.x, acc[1][0]);
            FMA2(acc[1][1], ay0.y, bx.y, acc[1][1]);
            FMA2(acc[2][0], ay1.x, bx.x, acc[2][0]);
            FMA2(acc[2][1], ay1.x, bx.y, acc[2][1]);
            FMA2(acc[3][0], ay1.y, bx.x, acc[3][0]);
            FMA2(acc[3][1], ay1.y, bx.y, acc[3][1]);
        }
        if (p + 1 < NP_) __syncthreads();  // gen(p+2) may overwrite buf
    }

    // ---- Store: each h-row = 4 consecutive floats = 1x STG.128 ----
    #pragma unroll
    for (int i = 0; i < 4; i++) {
        const int h = hbase + ty * 4 + i;
        const int w = wbase + tx * 4;
        float4* dst = (float4*)(out + ((size_t)b * HW_ + h) * HW_ + w);
        *dst = *(const float4*)&acc[i][0];
    }
}

// ---------------------------------------------------------------------------
// Launch: single kernel, single graph node.
// ---------------------------------------------------------------------------
extern "C" void kernel_launch(void* const* d_in, const int* in_sizes, int n_in,
                              void* d_out, int out_size)
{
    // d_in[0] = batch_images (unused, shape only)
    const float* labels = (const float*)d_in[1];  // (4, 64, 2)
    const float* sigma  = (const float*)d_in[2];  // (1,)
    float* out = (float*)d_out;                   // (4, 1, 512, 512)

    dim3 grid(HW_ / TW_, HW_ / TH_, B_);   // (8, 8, 4) = 256 CTAs
    density_kernel<<<grid, 256>>>(out, labels, sigma);
}